// round 8
// baseline (speedup 1.0000x reference)
#include <cuda_runtime.h>
#include <cuda_fp16.h>

#define F_IN 128
#define FS   64
#define NH   8
#define NMAX 4096
#define NBLK 148
#define NTHR 1024

// persistent scratch (allocations forbidden)
__device__ __half   g_hh[NMAX][2 * NH];  // node features fp16, PRE-SCALED by 0.5
__device__ double   g_s1, g_s2;          // gate sum / sum of squares
__device__ unsigned g_count = 0;         // grid-barrier arrivals
__device__ unsigned g_gen   = 0;         // grid-barrier generation (monotone)
__device__ unsigned g_done  = 0;         // last-block ticket

__device__ __forceinline__ unsigned h2_to_u(__half2 h) { return *(unsigned*)&h; }
__device__ __forceinline__ __half2 u_to_h2(unsigned u) { return *(__half2*)&u; }
// packed pair of tanh.approx on fp16x2 : one MUFU op for two activations
__device__ __forceinline__ __half2 tanh2_fast(__half2 x) {
    unsigned r, xi = h2_to_u(x);
    asm("tanh.approx.f16x2 %0, %1;" : "=r"(r) : "r"(xi));
    return u_to_h2(r);
}

// sense-reversal grid barrier; safe because grid==NBLK<=#SMs (all co-resident)
__device__ __forceinline__ void grid_barrier() {
    __threadfence();
    __syncthreads();
    if (threadIdx.x == 0) {
        unsigned my = *(volatile unsigned*)&g_gen;
        if (atomicAdd(&g_count, 1u) == NBLK - 1) {
            g_count = 0;
            __threadfence();
            atomicAdd(&g_gen, 1u);
        } else {
            while (*(volatile unsigned*)&g_gen == my) { }
            __threadfence();
        }
    }
    __syncthreads();
}

__global__ void __launch_bounds__(NTHR, 1)
fused_kernel(const float* __restrict__ x,
             const float* __restrict__ Wlin,
             const float* __restrict__ blin,
             const float* __restrict__ W1,
             const float* __restrict__ b1,
             const float* __restrict__ W2,
             const float* __restrict__ b2,
             const int*   __restrict__ ei,
             const float* __restrict__ u,
             float* __restrict__ out,
             int N, int E, int out_size) {
    __shared__ float   WlinS[FS][F_IN];     // 32 KB
    __shared__ float   MsP[F_IN][17];       // fused weight, padded rows (conflict-free)
    __shared__ float   cs[2 * NH];          // fused bias
    __shared__ float   W1s[NH][2 * FS];     // 4 KB
    __shared__ __half2 w2p[NH / 2];         // packed 0.25*w2 pairs
    __shared__ float   b2p;                 // 0.5*b2 + 0.25*sum(w2)
    __shared__ float   r1[NTHR / 32], r2[NTHR / 32];

    const int tid  = threadIdx.x;
    const int gtid = blockIdx.x * NTHR + tid;

    // ---- stage Wlin + W1 into smem (coalesced), pack constants ----
    {   // 8192 floats = 2048 float4
        const float4* src = (const float4*)Wlin;
        float4* dst = (float4*)&WlinS[0][0];
        dst[tid]        = src[tid];
        dst[tid + 1024] = src[tid + 1024];
    }
    if (tid < NH * 2 * FS) W1s[tid / (2 * FS)][tid % (2 * FS)] = W1[tid];
    if (tid < NH / 2)
        w2p[tid] = __floats2half2_rn(0.25f * W2[2 * tid], 0.25f * W2[2 * tid + 1]);
    if (tid == 0) {
        float s = 0.0f;
        #pragma unroll
        for (int h = 0; h < NH; h++) s += W2[h];
        b2p = 0.5f * b2[0] + 0.25f * s;
    }
    if (blockIdx.x == 0 && tid == 0) { g_s1 = 0.0; g_s2 = 0.0; }

    // ---- prefetch this thread's edge (independent of everything else) ----
    int   pe_i = 0, pe_j = 0;
    float pe_u = 0.0f;
    const int e0 = gtid;               // NBLK*NTHR = 151552 >= E
    if (e0 < E) { pe_i = ei[e0]; pe_j = ei[E + e0]; pe_u = u[e0]; }

    __syncthreads();

    // ---- phase 1 (per-block, redundant): M = W1 @ Wlin ----
    // all 1024 threads, 2 adjacent k-columns each: short 128-FMA chains
    {
        int t  = tid & 15;
        int k2 = tid >> 4;                 // 0..63 -> columns 2k2, 2k2+1
        int hrow = t & (NH - 1);
        int off  = (t < NH) ? 0 : FS;
        float a0 = 0.f, a1 = 0.f, b0 = 0.f, b1v = 0.f;
        #pragma unroll 16
        for (int f = 0; f < FS; f += 2) {
            float2 wlA = *(const float2*)&WlinS[f    ][k2 * 2];
            float2 wlB = *(const float2*)&WlinS[f + 1][k2 * 2];
            float w1A = W1s[hrow][off + f];
            float w1B = W1s[hrow][off + f + 1];
            a0 = fmaf(w1A, wlA.x, a0);
            a1 = fmaf(w1A, wlA.y, a1);
            b0 = fmaf(w1B, wlB.x, b0);
            b1v= fmaf(w1B, wlB.y, b1v);
        }
        MsP[2 * k2    ][t] = a0 + b0;
        MsP[2 * k2 + 1][t] = a1 + b1v;
    }
    if (tid < 2 * NH) {                    // fused bias (16 threads, tiny)
        int t = tid, hrow = t & (NH - 1), off = (t < NH) ? 0 : FS;
        float acc = (t < NH) ? b1[t] : 0.0f;
        for (int f = 0; f < FS; f++)
            acc = fmaf(W1s[hrow][off + f], blin[f], acc);
        cs[t] = acc;
    }
    __syncthreads();

    // ---- phase 2: node features, ONE WARP PER NODE ----
    // lane = t*2+half ; half covers k-chunks {half, half+2, half+4, half+6} (16 floats each)
    {
        int w    = tid >> 5;               // 0..31
        int lane = tid & 31;
        int t    = lane >> 1;
        int half = lane & 1;
        int node = blockIdx.x + NBLK * w;
        if (node < N) {
            const float4* xr = (const float4*)(x + (size_t)node * F_IN);
            float c0 = (half == 0) ? cs[t] : 0.0f;
            float c1 = 0.f, c2 = 0.f, c3 = 0.f;
            #pragma unroll
            for (int ci = 0; ci < 4; ci++) {
                int kb  = 32 * ci + 16 * half;     // chunk base (16 floats)
                int k4b = kb >> 2;
                float4 v0 = xr[k4b + 0], v1 = xr[k4b + 1];
                float4 v2 = xr[k4b + 2], v3 = xr[k4b + 3];
                c0 = fmaf(v0.x, MsP[kb+ 0][t], c0); c0 = fmaf(v0.y, MsP[kb+ 1][t], c0);
                c0 = fmaf(v0.z, MsP[kb+ 2][t], c0); c0 = fmaf(v0.w, MsP[kb+ 3][t], c0);
                c1 = fmaf(v1.x, MsP[kb+ 4][t], c1); c1 = fmaf(v1.y, MsP[kb+ 5][t], c1);
                c1 = fmaf(v1.z, MsP[kb+ 6][t], c1); c1 = fmaf(v1.w, MsP[kb+ 7][t], c1);
                c2 = fmaf(v2.x, MsP[kb+ 8][t], c2); c2 = fmaf(v2.y, MsP[kb+ 9][t], c2);
                c2 = fmaf(v2.z, MsP[kb+10][t], c2); c2 = fmaf(v2.w, MsP[kb+11][t], c2);
                c3 = fmaf(v3.x, MsP[kb+12][t], c3); c3 = fmaf(v3.y, MsP[kb+13][t], c3);
                c3 = fmaf(v3.z, MsP[kb+14][t], c3); c3 = fmaf(v3.w, MsP[kb+15][t], c3);
            }
            float acc = (c0 + c1) + (c2 + c3);
            float full  = acc + __shfl_xor_sync(0xffffffffu, acc, 1);  // both halves
            float fullN = __shfl_down_sync(0xffffffffu, full, 2);      // t+1 partner
            if ((lane & 3) == 0)   // lanes 0,4,...,28 -> t = 0,2,...,14
                ((__half2*)g_hh[node])[lane >> 2] =
                    __floats2half2_rn(0.5f * full, 0.5f * fullN);
        }
    }
    grid_barrier();   // g_hh complete & visible

    // ---- phase 3: one edge per thread ----
    float ls1 = 0.0f, ls2 = 0.0f;
    if (e0 < E) {
        const uint4* ri = (const uint4*)g_hh[pe_i];
        const uint4* rj = (const uint4*)g_hh[pe_j];
        uint4 i_lo = ri[0], i_hi = ri[1];   // 0.5*h1_i , 0.5*h2_i
        uint4 j_lo = rj[0], j_hi = rj[1];   // 0.5*h1_j , 0.5*h2_j

        const __half2* il = (const __half2*)&i_lo;
        const __half2* ih = (const __half2*)&i_hi;
        const __half2* jl = (const __half2*)&j_lo;
        const __half2* jh = (const __half2*)&j_hi;

        // accumulate sij/2 and sji/2 in half2 (w2p = w2/4, g_hh = h/2)
        __half2 aij = __floats2half2_rn(0.0f, 0.0f);
        __half2 aji = aij;
        #pragma unroll
        for (int q = 0; q < 4; q++) {
            __half2 ta = tanh2_fast(__hadd2(il[q], jh[q]));
            __half2 tc = tanh2_fast(__hadd2(jl[q], ih[q]));
            __half2 w2q = w2p[q];
            aij = __hfma2(w2q, ta, aij);
            aji = __hfma2(w2q, tc, aji);
        }
        float2 fij = __half22float2(aij);
        float2 fji = __half22float2(aji);
        float sp_ij = b2p + fij.x + fij.y;   // = sij/2
        float sp_ji = b2p + fji.x + fji.y;   // = sji/2

        // two outer sigmoids in one f16x2 tanh
        __half2 sp  = __floats2half2_rn(sp_ij, sp_ji);
        float2 thf  = __half22float2(tanh2_fast(sp));
        float w = fmaf(0.25f, thf.x + thf.y, 0.5f);

        // gate = 1/(1 + ((1-eps)/eps)^2 * e^{-2w}),  eps = 0.9999 - 0.9998*u
        float eps     = fmaf(-0.9998f, pe_u, 0.9999f);
        float onemeps = fmaf( 0.9998f, pe_u, 0.0001f);
        float q  = __fdividef(onemeps, eps);
        float a  = q * q * __expf(-2.0f * w);
        float g  = __fdividef(1.0f, 1.0f + a);
        out[e0] = g;
        ls1 = g;
        ls2 = g * g;
    }

    // block reduction of (sum, sumsq)
    #pragma unroll
    for (int o = 16; o > 0; o >>= 1) {
        ls1 += __shfl_down_sync(0xffffffffu, ls1, o);
        ls2 += __shfl_down_sync(0xffffffffu, ls2, o);
    }
    int lane = tid & 31, wid = tid >> 5;
    if (lane == 0) { r1[wid] = ls1; r2[wid] = ls2; }
    __syncthreads();
    if (tid == 0) {
        float a = 0.0f, b = 0.0f;
        #pragma unroll
        for (int w = 0; w < NTHR / 32; w++) { a += r1[w]; b += r2[w]; }
        atomicAdd(&g_s1, (double)a);
        atomicAdd(&g_s2, (double)b);
        __threadfence();
        if (atomicAdd(&g_done, 1u) == NBLK - 1) {   // last block finalizes
            g_done = 0;
            __threadfence();
            double s1 = atomicAdd(&g_s1, 0.0);
            double s2 = atomicAdd(&g_s2, 0.0);
            double mean = s1 / (double)E;
            out[out_size - 1] = (float)((s2 - s1 * mean) / (double)(E - 1));
        }
    }
}

extern "C" void kernel_launch(void* const* d_in, const int* in_sizes, int n_in,
                              void* d_out, int out_size) {
    const float* x    = (const float*)d_in[0];   // [N, 128]
    const float* Wlin = (const float*)d_in[1];   // [64, 128]
    const float* blin = (const float*)d_in[2];   // [64]
    const float* W1   = (const float*)d_in[3];   // [8, 128]
    const float* b1   = (const float*)d_in[4];   // [8]
    const float* W2   = (const float*)d_in[5];   // [8]
    const float* b2   = (const float*)d_in[6];   // [1]
    const int*   ei   = (const int*)d_in[7];     // [2, E]
    const float* u    = (const float*)d_in[8];   // [E]

    int N = in_sizes[0] / F_IN;
    int E = in_sizes[8];

    fused_kernel<<<NBLK, NTHR>>>(x, Wlin, blin, W1, b1, W2, b2, ei, u,
                                 (float*)d_out, N, E, out_size);
}

// round 9
// speedup vs baseline: 1.1753x; 1.1753x over previous
#include <cuda_runtime.h>
#include <cuda_fp16.h>

#define F_IN 128
#define FS   64
#define NH   8
#define NMAX 4096

// persistent scratch (allocations forbidden)
__device__ __half   g_hh[NMAX][2 * NH];  // node features fp16, PRE-SCALED by 0.5
__device__ double   g_s1, g_s2;          // gate sum / sum of squares
__device__ unsigned g_done = 0;          // last-block ticket (kernel B)

__device__ __forceinline__ unsigned h2_to_u(__half2 h) { return *(unsigned*)&h; }
__device__ __forceinline__ __half2 u_to_h2(unsigned u) { return *(__half2*)&u; }
// packed pair of tanh.approx on fp16x2 : one MUFU op for two activations
__device__ __forceinline__ __half2 tanh2_fast(__half2 x) {
    unsigned r, xi = h2_to_u(x);
    asm("tanh.approx.f16x2 %0, %1;" : "=r"(r) : "r"(xi));
    return u_to_h2(r);
}

// ---------------------------------------------------------------------------
// Kernel A: prep (redundant per block) + node features.  512 thr, 32 nodes/blk
// ---------------------------------------------------------------------------
__global__ void __launch_bounds__(512)
node_kernel(const float* __restrict__ x,
            const float* __restrict__ Wlin,
            const float* __restrict__ blin,
            const float* __restrict__ W1,
            const float* __restrict__ b1,
            int N) {
    __shared__ float WlinS[FS][F_IN];     // 32 KB
    __shared__ float Ms[F_IN][2 * NH];    // fused weight, [k][t]
    __shared__ float cs[2 * NH];          // fused bias
    __shared__ float W1s[NH][2 * FS];     // 4 KB

    const int tid = threadIdx.x;

    // stage Wlin (coalesced float4) + W1
    {
        const float4* src = (const float4*)Wlin;
        float4* dst = (float4*)&WlinS[0][0];
        #pragma unroll
        for (int r = 0; r < 4; r++) dst[tid + 512 * r] = src[tid + 512 * r];
    }
    {
        W1s[tid >> 7][(tid & 127)]       = W1[tid];
        W1s[(tid + 512) >> 7][tid & 127] = W1[tid + 512];
    }
    if (blockIdx.x == 0 && tid == 0) { g_s1 = 0.0; g_s2 = 0.0; }
    __syncthreads();

    // prep: M = W1 @ Wlin  (512 threads, 4 k-columns each)
    {
        int t  = tid & 15;
        int k4 = tid >> 4;                 // 0..31 -> columns 4*k4..4*k4+3
        int hrow = t & (NH - 1);
        int off  = (t < NH) ? 0 : FS;
        float a0 = 0.f, a1 = 0.f, a2 = 0.f, a3 = 0.f;
        #pragma unroll 8
        for (int f = 0; f < FS; f++) {
            float4 wl = *(const float4*)&WlinS[f][k4 * 4];
            float w1v = W1s[hrow][off + f];
            a0 = fmaf(w1v, wl.x, a0);
            a1 = fmaf(w1v, wl.y, a1);
            a2 = fmaf(w1v, wl.z, a2);
            a3 = fmaf(w1v, wl.w, a3);
        }
        Ms[4 * k4 + 0][t] = a0;
        Ms[4 * k4 + 1][t] = a1;
        Ms[4 * k4 + 2][t] = a2;
        Ms[4 * k4 + 3][t] = a3;
    }
    if (tid < 2 * NH) {
        int t = tid, hrow = t & (NH - 1), off = (t < NH) ? 0 : FS;
        float acc = (t < NH) ? b1[t] : 0.0f;
        for (int f = 0; f < FS; f++)
            acc = fmaf(W1s[hrow][off + f], blin[f], acc);
        cs[t] = acc;
    }
    __syncthreads();

    // node features: one (node, t) per thread; 32 nodes per block
    {
        int g = tid >> 4;                  // 0..31
        int t = tid & 15;
        int node = blockIdx.x * 32 + g;
        bool valid = (node < N);
        float acc = 0.0f;
        if (valid) {
            const float4* xr = (const float4*)(x + (size_t)node * F_IN);
            float b0 = 0.f, b1a = 0.f, b2a = 0.f, b3 = 0.f;
            #pragma unroll
            for (int k4 = 0; k4 < F_IN / 4; k4 += 4) {
                float4 v0 = xr[k4 + 0], v1 = xr[k4 + 1];
                float4 v2 = xr[k4 + 2], v3 = xr[k4 + 3];
                b0 = fmaf(v0.x, Ms[4*k4+ 0][t], b0); b0 = fmaf(v0.y, Ms[4*k4+ 1][t], b0);
                b0 = fmaf(v0.z, Ms[4*k4+ 2][t], b0); b0 = fmaf(v0.w, Ms[4*k4+ 3][t], b0);
                b1a= fmaf(v1.x, Ms[4*k4+ 4][t], b1a);b1a= fmaf(v1.y, Ms[4*k4+ 5][t], b1a);
                b1a= fmaf(v1.z, Ms[4*k4+ 6][t], b1a);b1a= fmaf(v1.w, Ms[4*k4+ 7][t], b1a);
                b2a= fmaf(v2.x, Ms[4*k4+ 8][t], b2a);b2a= fmaf(v2.y, Ms[4*k4+ 9][t], b2a);
                b2a= fmaf(v2.z, Ms[4*k4+10][t], b2a);b2a= fmaf(v2.w, Ms[4*k4+11][t], b2a);
                b3 = fmaf(v3.x, Ms[4*k4+12][t], b3); b3 = fmaf(v3.y, Ms[4*k4+13][t], b3);
                b3 = fmaf(v3.z, Ms[4*k4+14][t], b3); b3 = fmaf(v3.w, Ms[4*k4+15][t], b3);
            }
            acc = 0.5f * (cs[t] + ((b0 + b1a) + (b2a + b3)));   // pre-scale by 0.5
        }
        float accN = __shfl_down_sync(0xffffffffu, acc, 1);
        if (valid && !(t & 1))
            ((__half2*)g_hh[node])[t >> 1] = __floats2half2_rn(acc, accN);
    }
}

// ---------------------------------------------------------------------------
// Kernel B: edges + variance.  256 thr/block, one edge per thread.
// ---------------------------------------------------------------------------
__global__ void __launch_bounds__(256)
edge_kernel(const int*   __restrict__ ei,
            const float* __restrict__ u,
            const float* __restrict__ W2,
            const float* __restrict__ b2,
            float* __restrict__ out,
            int E, int out_size, int nblk) {
    __shared__ float r1[8], r2[8];

    const int tid = threadIdx.x;
    const int e0  = blockIdx.x * 256 + tid;

    // per-thread constants (broadcast loads, L2/const-cached)
    __half2 w2p[NH / 2];
    #pragma unroll
    for (int q = 0; q < NH / 2; q++)
        w2p[q] = __floats2half2_rn(0.25f * W2[2 * q], 0.25f * W2[2 * q + 1]);
    float b2p = 0.5f * b2[0];
    #pragma unroll
    for (int h = 0; h < NH; h++) b2p += 0.25f * W2[h];

    float ls1 = 0.0f, ls2 = 0.0f;
    if (e0 < E) {
        int i = ei[e0];
        int j = ei[E + e0];
        float uu = u[e0];

        uint4 i_lo = ((const uint4*)g_hh[i])[0];
        uint4 i_hi = ((const uint4*)g_hh[i])[1];
        uint4 j_lo = ((const uint4*)g_hh[j])[0];
        uint4 j_hi = ((const uint4*)g_hh[j])[1];

        const __half2* il = (const __half2*)&i_lo;
        const __half2* ih = (const __half2*)&i_hi;
        const __half2* jl = (const __half2*)&j_lo;
        const __half2* jh = (const __half2*)&j_hi;

        // accumulate sij/2 and sji/2 in half2 (w2p = w2/4, g_hh = h/2)
        __half2 aij = __floats2half2_rn(0.0f, 0.0f);
        __half2 aji = aij;
        #pragma unroll
        for (int q = 0; q < 4; q++) {
            __half2 ta = tanh2_fast(__hadd2(il[q], jh[q]));
            __half2 tc = tanh2_fast(__hadd2(jl[q], ih[q]));
            aij = __hfma2(w2p[q], ta, aij);
            aji = __hfma2(w2p[q], tc, aji);
        }
        float2 fij = __half22float2(aij);
        float2 fji = __half22float2(aji);
        float sp_ij = b2p + fij.x + fij.y;   // = sij/2
        float sp_ji = b2p + fji.x + fji.y;   // = sji/2

        // two outer sigmoids in one f16x2 tanh
        __half2 sp = __floats2half2_rn(sp_ij, sp_ji);
        float2 thf = __half22float2(tanh2_fast(sp));
        float w = fmaf(0.25f, thf.x + thf.y, 0.5f);

        // gate = 1/(1 + ((1-eps)/eps)^2 * e^{-2w}),  eps = 0.9999 - 0.9998*u
        float eps     = fmaf(-0.9998f, uu, 0.9999f);
        float onemeps = fmaf( 0.9998f, uu, 0.0001f);
        float q  = __fdividef(onemeps, eps);
        float a  = q * q * __expf(-2.0f * w);
        float g  = __fdividef(1.0f, 1.0f + a);
        out[e0] = g;
        ls1 = g;
        ls2 = g * g;
    }

    // block reduction of (sum, sumsq)
    #pragma unroll
    for (int o = 16; o > 0; o >>= 1) {
        ls1 += __shfl_down_sync(0xffffffffu, ls1, o);
        ls2 += __shfl_down_sync(0xffffffffu, ls2, o);
    }
    int lane = tid & 31, wid = tid >> 5;
    if (lane == 0) { r1[wid] = ls1; r2[wid] = ls2; }
    __syncthreads();
    if (tid == 0) {
        float a = 0.0f, b = 0.0f;
        #pragma unroll
        for (int w = 0; w < 8; w++) { a += r1[w]; b += r2[w]; }
        atomicAdd(&g_s1, (double)a);
        atomicAdd(&g_s2, (double)b);
        __threadfence();
        // last block computes the variance
        if (atomicAdd(&g_done, 1u) == (unsigned)nblk - 1) {
            g_done = 0;                      // reset for next graph replay
            __threadfence();
            double s1 = atomicAdd(&g_s1, 0.0);
            double s2 = atomicAdd(&g_s2, 0.0);
            double mean = s1 / (double)E;
            out[out_size - 1] = (float)((s2 - s1 * mean) / (double)(E - 1));
        }
    }
}

extern "C" void kernel_launch(void* const* d_in, const int* in_sizes, int n_in,
                              void* d_out, int out_size) {
    const float* x    = (const float*)d_in[0];   // [N, 128]
    const float* Wlin = (const float*)d_in[1];   // [64, 128]
    const float* blin = (const float*)d_in[2];   // [64]
    const float* W1   = (const float*)d_in[3];   // [8, 128]
    const float* b1   = (const float*)d_in[4];   // [8]
    const float* W2   = (const float*)d_in[5];   // [8]
    const float* b2   = (const float*)d_in[6];   // [1]
    const int*   ei   = (const int*)d_in[7];     // [2, E]
    const float* u    = (const float*)d_in[8];   // [E]

    int N = in_sizes[0] / F_IN;
    int E = in_sizes[8];
    float* out = (float*)d_out;

    int blocksA = (N + 31) / 32;
    int blocksB = (E + 255) / 256;

    node_kernel<<<blocksA, 512>>>(x, Wlin, blin, W1, b1, N);
    edge_kernel<<<blocksB, 256>>>(ei, u, W2, b2, out, E, out_size, blocksB);
}

// round 10
// speedup vs baseline: 1.2829x; 1.0915x over previous
#include <cuda_runtime.h>
#include <cuda_fp16.h>

#define F_IN 128
#define FS   64
#define NH   8
#define NMAX 4096

// persistent scratch (allocations forbidden)
__device__ __half   g_hh[NMAX][2 * NH];  // node features fp16, PRE-SCALED by 0.5
__device__ double   g_s1, g_s2;          // gate sum / sum of squares
__device__ unsigned g_done = 0;          // last-block ticket (kernel B)

__device__ __forceinline__ unsigned h2_to_u(__half2 h) { return *(unsigned*)&h; }
__device__ __forceinline__ __half2 u_to_h2(unsigned u) { return *(__half2*)&u; }
// packed pair of tanh.approx on fp16x2 : one MUFU op for two activations
__device__ __forceinline__ __half2 tanh2_fast(__half2 x) {
    unsigned r, xi = h2_to_u(x);
    asm("tanh.approx.f16x2 %0, %1;" : "=r"(r) : "r"(xi));
    return u_to_h2(r);
}

// ---------------------------------------------------------------------------
// Kernel A: prep (redundant per block) + node features.  512 thr, 32 nodes/blk
// ---------------------------------------------------------------------------
__global__ void __launch_bounds__(512)
node_kernel(const float* __restrict__ x,
            const float* __restrict__ Wlin,
            const float* __restrict__ blin,
            const float* __restrict__ W1,
            const float* __restrict__ b1,
            int N) {
    __shared__ float WlinS[FS][F_IN];     // 32 KB
    __shared__ float Ms[F_IN][2 * NH];    // fused weight, [k][t]
    __shared__ float cs[2 * NH];          // fused bias
    __shared__ float W1s[NH][2 * FS];     // 4 KB

    const int tid = threadIdx.x;

    // stage Wlin (coalesced float4) + W1
    {
        const float4* src = (const float4*)Wlin;
        float4* dst = (float4*)&WlinS[0][0];
        #pragma unroll
        for (int r = 0; r < 4; r++) dst[tid + 512 * r] = src[tid + 512 * r];
    }
    {
        W1s[tid >> 7][(tid & 127)]       = W1[tid];
        W1s[(tid + 512) >> 7][tid & 127] = W1[tid + 512];
    }
    if (blockIdx.x == 0 && tid == 0) { g_s1 = 0.0; g_s2 = 0.0; }
    __syncthreads();

    // prep: M = W1 @ Wlin  (512 threads, 4 k-columns each)
    {
        int t  = tid & 15;
        int k4 = tid >> 4;                 // 0..31 -> columns 4*k4..4*k4+3
        int hrow = t & (NH - 1);
        int off  = (t < NH) ? 0 : FS;
        float a0 = 0.f, a1 = 0.f, a2 = 0.f, a3 = 0.f;
        #pragma unroll 8
        for (int f = 0; f < FS; f++) {
            float4 wl = *(const float4*)&WlinS[f][k4 * 4];
            float w1v = W1s[hrow][off + f];
            a0 = fmaf(w1v, wl.x, a0);
            a1 = fmaf(w1v, wl.y, a1);
            a2 = fmaf(w1v, wl.z, a2);
            a3 = fmaf(w1v, wl.w, a3);
        }
        Ms[4 * k4 + 0][t] = a0;
        Ms[4 * k4 + 1][t] = a1;
        Ms[4 * k4 + 2][t] = a2;
        Ms[4 * k4 + 3][t] = a3;
    }
    if (tid < 2 * NH) {
        int t = tid, hrow = t & (NH - 1), off = (t < NH) ? 0 : FS;
        float acc = (t < NH) ? b1[t] : 0.0f;
        for (int f = 0; f < FS; f++)
            acc = fmaf(W1s[hrow][off + f], blin[f], acc);
        cs[t] = acc;
    }
    __syncthreads();

    // node features: one (node, t) per thread; 32 nodes per block
    {
        int g = tid >> 4;                  // 0..31
        int t = tid & 15;
        int node = blockIdx.x * 32 + g;
        bool valid = (node < N);
        float acc = 0.0f;
        if (valid) {
            const float4* xr = (const float4*)(x + (size_t)node * F_IN);
            float b0 = 0.f, b1a = 0.f, b2a = 0.f, b3 = 0.f;
            #pragma unroll
            for (int k4 = 0; k4 < F_IN / 4; k4 += 4) {
                float4 v0 = xr[k4 + 0], v1 = xr[k4 + 1];
                float4 v2 = xr[k4 + 2], v3 = xr[k4 + 3];
                b0 = fmaf(v0.x, Ms[4*k4+ 0][t], b0); b0 = fmaf(v0.y, Ms[4*k4+ 1][t], b0);
                b0 = fmaf(v0.z, Ms[4*k4+ 2][t], b0); b0 = fmaf(v0.w, Ms[4*k4+ 3][t], b0);
                b1a= fmaf(v1.x, Ms[4*k4+ 4][t], b1a);b1a= fmaf(v1.y, Ms[4*k4+ 5][t], b1a);
                b1a= fmaf(v1.z, Ms[4*k4+ 6][t], b1a);b1a= fmaf(v1.w, Ms[4*k4+ 7][t], b1a);
                b2a= fmaf(v2.x, Ms[4*k4+ 8][t], b2a);b2a= fmaf(v2.y, Ms[4*k4+ 9][t], b2a);
                b2a= fmaf(v2.z, Ms[4*k4+10][t], b2a);b2a= fmaf(v2.w, Ms[4*k4+11][t], b2a);
                b3 = fmaf(v3.x, Ms[4*k4+12][t], b3); b3 = fmaf(v3.y, Ms[4*k4+13][t], b3);
                b3 = fmaf(v3.z, Ms[4*k4+14][t], b3); b3 = fmaf(v3.w, Ms[4*k4+15][t], b3);
            }
            acc = 0.5f * (cs[t] + ((b0 + b1a) + (b2a + b3)));   // pre-scale by 0.5
        }
        float accN = __shfl_down_sync(0xffffffffu, acc, 1);
        if (valid && !(t & 1))
            ((__half2*)g_hh[node])[t >> 1] = __floats2half2_rn(acc, accN);
    }
}

// ---------------------------------------------------------------------------
// Kernel B: edges + variance.  PDL: prologue overlaps with kernel A.
// ---------------------------------------------------------------------------
__global__ void __launch_bounds__(256)
edge_kernel(const int*   __restrict__ ei,
            const float* __restrict__ u,
            const float* __restrict__ W2,
            const float* __restrict__ b2,
            float* __restrict__ out,
            int E, int out_size, int nblk) {
    __shared__ float r1[8], r2[8];

    const int tid = threadIdx.x;
    const int e0  = blockIdx.x * 256 + tid;

    // ---- PDL prologue: everything independent of g_hh ----
    int   i = 0, j = 0;
    float uu = 0.0f;
    if (e0 < E) { i = ei[e0]; j = ei[E + e0]; uu = u[e0]; }

    __half2 w2p[NH / 2];
    #pragma unroll
    for (int q = 0; q < NH / 2; q++)
        w2p[q] = __floats2half2_rn(0.25f * W2[2 * q], 0.25f * W2[2 * q + 1]);
    float b2p = 0.5f * b2[0];
    #pragma unroll
    for (int h = 0; h < NH; h++) b2p += 0.25f * W2[h];

    // precompute the u-dependent part of the gate
    float eps     = fmaf(-0.9998f, uu, 0.9999f);
    float onemeps = fmaf( 0.9998f, uu, 0.0001f);
    float qr  = __fdividef(onemeps, eps);
    float q2  = qr * qr;

    // ---- wait for kernel A's g_hh stores (implicit completion trigger) ----
    cudaGridDependencySynchronize();

    float ls1 = 0.0f, ls2 = 0.0f;
    if (e0 < E) {
        uint4 i_lo = ((const uint4*)g_hh[i])[0];
        uint4 i_hi = ((const uint4*)g_hh[i])[1];
        uint4 j_lo = ((const uint4*)g_hh[j])[0];
        uint4 j_hi = ((const uint4*)g_hh[j])[1];

        const __half2* il = (const __half2*)&i_lo;
        const __half2* ih = (const __half2*)&i_hi;
        const __half2* jl = (const __half2*)&j_lo;
        const __half2* jh = (const __half2*)&j_hi;

        // accumulate sij/2 and sji/2 in half2 (w2p = w2/4, g_hh = h/2)
        __half2 aij = __floats2half2_rn(0.0f, 0.0f);
        __half2 aji = aij;
        #pragma unroll
        for (int q = 0; q < 4; q++) {
            __half2 ta = tanh2_fast(__hadd2(il[q], jh[q]));
            __half2 tc = tanh2_fast(__hadd2(jl[q], ih[q]));
            aij = __hfma2(w2p[q], ta, aij);
            aji = __hfma2(w2p[q], tc, aji);
        }
        float2 fij = __half22float2(aij);
        float2 fji = __half22float2(aji);
        float sp_ij = b2p + fij.x + fij.y;   // = sij/2
        float sp_ji = b2p + fji.x + fji.y;   // = sji/2

        // two outer sigmoids in one f16x2 tanh
        __half2 sp = __floats2half2_rn(sp_ij, sp_ji);
        float2 thf = __half22float2(tanh2_fast(sp));
        float w = fmaf(0.25f, thf.x + thf.y, 0.5f);

        // gate = 1/(1 + ((1-eps)/eps)^2 * e^{-2w})
        float a  = q2 * __expf(-2.0f * w);
        float g  = __fdividef(1.0f, 1.0f + a);
        out[e0] = g;
        ls1 = g;
        ls2 = g * g;
    }

    // block reduction of (sum, sumsq)
    #pragma unroll
    for (int o = 16; o > 0; o >>= 1) {
        ls1 += __shfl_down_sync(0xffffffffu, ls1, o);
        ls2 += __shfl_down_sync(0xffffffffu, ls2, o);
    }
    int lane = tid & 31, wid = tid >> 5;
    if (lane == 0) { r1[wid] = ls1; r2[wid] = ls2; }
    __syncthreads();
    if (tid == 0) {
        float a = 0.0f, b = 0.0f;
        #pragma unroll
        for (int w = 0; w < 8; w++) { a += r1[w]; b += r2[w]; }
        atomicAdd(&g_s1, (double)a);
        atomicAdd(&g_s2, (double)b);
        __threadfence();
        // last block computes the variance
        if (atomicAdd(&g_done, 1u) == (unsigned)nblk - 1) {
            g_done = 0;                      // reset for next graph replay
            __threadfence();
            double s1 = atomicAdd(&g_s1, 0.0);
            double s2 = atomicAdd(&g_s2, 0.0);
            double mean = s1 / (double)E;
            out[out_size - 1] = (float)((s2 - s1 * mean) / (double)(E - 1));
        }
    }
}

extern "C" void kernel_launch(void* const* d_in, const int* in_sizes, int n_in,
                              void* d_out, int out_size) {
    const float* x    = (const float*)d_in[0];   // [N, 128]
    const float* Wlin = (const float*)d_in[1];   // [64, 128]
    const float* blin = (const float*)d_in[2];   // [64]
    const float* W1   = (const float*)d_in[3];   // [8, 128]
    const float* b1   = (const float*)d_in[4];   // [8]
    const float* W2   = (const float*)d_in[5];   // [8]
    const float* b2   = (const float*)d_in[6];   // [1]
    const int*   ei   = (const int*)d_in[7];     // [2, E]
    const float* u    = (const float*)d_in[8];   // [E]

    int N = in_sizes[0] / F_IN;
    int E = in_sizes[8];
    float* out = (float*)d_out;

    int blocksA = (N + 31) / 32;
    int blocksB = (E + 255) / 256;

    node_kernel<<<blocksA, 512>>>(x, Wlin, blin, W1, b1, N);

    // PDL launch: edge_kernel's prologue overlaps with node_kernel
    cudaLaunchConfig_t cfg = {};
    cfg.gridDim  = dim3((unsigned)blocksB);
    cfg.blockDim = dim3(256);
    cfg.dynamicSmemBytes = 0;
    cfg.stream = 0;
    cudaLaunchAttribute attrs[1];
    attrs[0].id = cudaLaunchAttributeProgrammaticStreamSerialization;
    attrs[0].val.programmaticStreamSerializationAllowed = 1;
    cfg.attrs = attrs;
    cfg.numAttrs = 1;
    cudaLaunchKernelEx(&cfg, edge_kernel, ei, u, W2, b2, out, E, out_size, blocksB);
}